// round 7
// baseline (speedup 1.0000x reference)
#include <cuda_runtime.h>
#include <cuda_bf16.h>
#include <cstdint>

#define N_NODES 8192
#define IN_F    256
#define HO      256   // H * OUT_F
#define NHEAD   4
#define OUTF    64

// ---------------- scratch (static device globals; no allocation) ----------------
__device__ float          g_support[(size_t)N_NODES * HO];       // fp32 support
__device__ __nv_bfloat16  g_support_bf[(size_t)N_NODES * HO];    // bf16 [m][c]
__device__ float2         g_E1p[(size_t)N_NODES * NHEAD];        // [m*4+h] = (exp f1, exp .2f1)
__device__ float2         g_E2p[(size_t)N_NODES * NHEAD];        // [n*4+h]
// packed bf16 tables for the P-build:
__device__ uint2          g_E1b[(size_t)(N_NODES / 2) * NHEAD];  // [mp*4+h]: {bf162(e_m,e_m1), bf162(ep_m,ep_m1)}
__device__ uint2          g_E2b[(size_t)N_NODES * NHEAD];        // [n*4+h]:  {bf162(e,e), bf162(ep,ep)}

// ============================ PTX helpers ============================
__device__ __forceinline__ uint32_t smem_u32(const void* p) {
    uint32_t a;
    asm("{ .reg .u64 t; cvta.to.shared.u64 t, %1; cvt.u32.u64 %0, t; }" : "=r"(a) : "l"(p));
    return a;
}
__device__ __forceinline__ void ldsm_x4(uint32_t* r, uint32_t addr) {
    asm volatile("ldmatrix.sync.aligned.m8n8.x4.shared.b16 {%0,%1,%2,%3}, [%4];"
        : "=r"(r[0]), "=r"(r[1]), "=r"(r[2]), "=r"(r[3]) : "r"(addr));
}
__device__ __forceinline__ void ldsm_x2t(uint32_t* r, uint32_t addr) {
    asm volatile("ldmatrix.sync.aligned.m8n8.x2.trans.shared.b16 {%0,%1}, [%2];"
        : "=r"(r[0]), "=r"(r[1]) : "r"(addr));
}
__device__ __forceinline__ void mma_bf16(float* d, const uint32_t* a, uint32_t b0, uint32_t b1) {
    asm volatile("mma.sync.aligned.m16n8k16.row.col.f32.bf16.bf16.f32 "
        "{%0,%1,%2,%3}, {%4,%5,%6,%7}, {%8,%9}, {%0,%1,%2,%3};"
        : "+f"(d[0]), "+f"(d[1]), "+f"(d[2]), "+f"(d[3])
        : "r"(a[0]), "r"(a[1]), "r"(a[2]), "r"(a[3]), "r"(b0), "r"(b1));
}
__device__ __forceinline__ __nv_bfloat162 b2(uint32_t u) { return *(__nv_bfloat162*)&u; }

// ---------------------------------------------------------------------------
// K1: fused GEMM: support fp32 + bf16 copy; proj term (+bias+proj_b) -> out.
// 128x128 tile, BK=8, 256 threads, 8x8 microtile.
// ---------------------------------------------------------------------------
__global__ void __launch_bounds__(256) gemm_kernel(
    const float* __restrict__ A, const float* __restrict__ W,
    const float* __restrict__ PW, const float* __restrict__ bias,
    const float* __restrict__ pb, float* __restrict__ out)
{
    __shared__ float As[8][132];
    __shared__ float Bs[8][132];

    const int tid = threadIdx.x;
    const int tx = tid & 15, ty = tid >> 4;
    const int j0 = blockIdx.x * 128;
    const int n0 = blockIdx.y * 128;
    const bool isproj = (j0 >= 256);

    const int a_row = tid >> 1, a_kq = (tid & 1) * 4;
    const int w_k = tid >> 5,  w_j  = (tid & 31) * 4;

    float acc[8][8];
    #pragma unroll
    for (int i = 0; i < 8; i++)
        #pragma unroll
        for (int j = 0; j < 8; j++) acc[i][j] = 0.f;

    for (int k0 = 0; k0 < IN_F; k0 += 8) {
        float4 av = *(const float4*)&A[(size_t)(n0 + a_row) * IN_F + k0 + a_kq];
        As[a_kq + 0][a_row] = av.x; As[a_kq + 1][a_row] = av.y;
        As[a_kq + 2][a_row] = av.z; As[a_kq + 3][a_row] = av.w;
        if (!isproj) {
            *(float4*)&Bs[w_k][w_j] = *(const float4*)&W[(size_t)(k0 + w_k) * HO + j0 + w_j];
        } else {
            float4 pv = *(const float4*)&PW[(size_t)(j0 - 256 + a_row) * IN_F + k0 + a_kq];
            Bs[a_kq + 0][a_row] = pv.x; Bs[a_kq + 1][a_row] = pv.y;
            Bs[a_kq + 2][a_row] = pv.z; Bs[a_kq + 3][a_row] = pv.w;
        }
        __syncthreads();

        #pragma unroll
        for (int k = 0; k < 8; k++) {
            float a[8], b[8];
            *(float4*)(a)     = *(const float4*)&As[k][ty * 8];
            *(float4*)(a + 4) = *(const float4*)&As[k][ty * 8 + 4];
            *(float4*)(b)     = *(const float4*)&Bs[k][tx * 8];
            *(float4*)(b + 4) = *(const float4*)&Bs[k][tx * 8 + 4];
            #pragma unroll
            for (int ii = 0; ii < 8; ii++)
                #pragma unroll
                for (int jj = 0; jj < 8; jj++)
                    acc[ii][jj] += a[ii] * b[jj];
        }
        __syncthreads();
    }

    if (!isproj) {
        #pragma unroll
        for (int ii = 0; ii < 8; ii++) {
            size_t base = (size_t)(n0 + ty * 8 + ii) * HO + j0 + tx * 8;
            *(float4*)&g_support[base]     = *(float4*)&acc[ii][0];
            *(float4*)&g_support[base + 4] = *(float4*)&acc[ii][4];
            uint4 u;
            __nv_bfloat162 b0 = __floats2bfloat162_rn(acc[ii][0], acc[ii][1]);
            __nv_bfloat162 b1 = __floats2bfloat162_rn(acc[ii][2], acc[ii][3]);
            __nv_bfloat162 b2v = __floats2bfloat162_rn(acc[ii][4], acc[ii][5]);
            __nv_bfloat162 b3 = __floats2bfloat162_rn(acc[ii][6], acc[ii][7]);
            u.x = *(unsigned*)&b0; u.y = *(unsigned*)&b1;
            u.z = *(unsigned*)&b2v; u.w = *(unsigned*)&b3;
            *(uint4*)((char*)g_support_bf + base * 2) = u;
        }
    } else {
        const int c0 = j0 - 256 + tx * 8;
        float bb[8];
        #pragma unroll
        for (int jj = 0; jj < 8; jj++) bb[jj] = bias[c0 + jj] + pb[c0 + jj];
        #pragma unroll
        for (int ii = 0; ii < 8; ii++) {
            size_t base = (size_t)(n0 + ty * 8 + ii) * HO + c0;
            float4 o0, o1;
            o0.x = acc[ii][0] + bb[0]; o0.y = acc[ii][1] + bb[1];
            o0.z = acc[ii][2] + bb[2]; o0.w = acc[ii][3] + bb[3];
            o1.x = acc[ii][4] + bb[4]; o1.y = acc[ii][5] + bb[5];
            o1.z = acc[ii][6] + bb[6]; o1.w = acc[ii][7] + bb[7];
            *(float4*)&out[base] = o0; *(float4*)&out[base + 4] = o1;
        }
    }
}

// ---------------------------------------------------------------------------
// K2: E tables (warp per (h,m))
// ---------------------------------------------------------------------------
__global__ void __launch_bounds__(256) fvec_kernel(
    const float* __restrict__ wu, const float* __restrict__ wv)
{
    const int warp = threadIdx.x >> 5, lane = threadIdx.x & 31;
    const int p = blockIdx.x * 8 + warp;
    const int m = p >> 2, h = p & 3;

    const size_t base = (size_t)m * HO + h * OUTF;
    float s0 = g_support[base + lane];
    float s1 = g_support[base + lane + 32];
    float u0 = wu[h * OUTF + lane], u1 = wu[h * OUTF + lane + 32];
    float v0 = wv[h * OUTF + lane], v1 = wv[h * OUTF + lane + 32];

    float d1 = s0 * u0 + s1 * u1;
    float d2 = s0 * v0 + s1 * v1;
    #pragma unroll
    for (int off = 16; off; off >>= 1) {
        d1 += __shfl_down_sync(0xffffffffu, d1, off);
        d2 += __shfl_down_sync(0xffffffffu, d2, off);
    }
    if (lane == 0) {
        g_E1p[(size_t)m * 4 + h] = make_float2(expf(d1), expf(0.2f * d1));
        g_E2p[(size_t)m * 4 + h] = make_float2(expf(d2), expf(0.2f * d2));
    }
}

// ---------------------------------------------------------------------------
// K2b: pack E tables to bf16x2 forms.
// ---------------------------------------------------------------------------
#define E1B_N ((N_NODES / 2) * NHEAD)
#define E2B_N (N_NODES * NHEAD)
__global__ void __launch_bounds__(256) pack_kernel()
{
    const int t = blockIdx.x * 256 + threadIdx.x;
    if (t < E1B_N) {
        const int mp = t >> 2, h = t & 3;
        float2 ea = g_E1p[(size_t)(2 * mp) * 4 + h];
        float2 eb = g_E1p[(size_t)(2 * mp + 1) * 4 + h];
        __nv_bfloat162 lo = __floats2bfloat162_rn(ea.x, eb.x);
        __nv_bfloat162 hi = __floats2bfloat162_rn(ea.y, eb.y);
        g_E1b[t] = make_uint2(*(uint32_t*)&lo, *(uint32_t*)&hi);
    } else if (t < E1B_N + E2B_N) {
        const int t2 = t - E1B_N;
        float2 e = g_E2p[t2];
        __nv_bfloat162 a = __floats2bfloat162_rn(e.x, e.x);
        __nv_bfloat162 b = __floats2bfloat162_rn(e.y, e.y);
        g_E2b[t2] = make_uint2(*(uint32_t*)&a, *(uint32_t*)&b);
    }
}

// ---------------------------------------------------------------------------
// K3: HMMA flash-style aggregation.
// CTA = 64 dst rows x 256 ch, 512 threads, grid 128.
// Per 64-m chunk: stage S [64m][256ch] bf16 (stride 528), build P 4 planes
// [64n][64m] bf16 (stride 144), then 16 warps (rg 0..3 x head 0..3) run
// mma.sync m16n8k16; denominator via ones-column MMA.
// ---------------------------------------------------------------------------
#define S_STRIDE 528
#define P_STRIDE 144
#define P_PLANE  (64 * P_STRIDE)
#define OFF_S    0
#define OFF_P    (64 * S_STRIDE)
#define SMEM_AGG (OFF_P + NHEAD * P_PLANE)   // 33792 + 36864 = 70656

__global__ void __launch_bounds__(512, 1) agg_kernel(
    const float* __restrict__ adj, float* __restrict__ out)
{
    extern __shared__ char smem[];
    const uint32_t sb = smem_u32(smem);
    const int tid  = threadIdx.x;
    const int lane = tid & 31, wid = tid >> 5;
    const int n0   = blockIdx.x * 64;

    // ---- build mapping: thread -> (row bn, m-octet bq) ----
    const int bn = tid >> 3;
    const int bq = tid & 7;
    uint4 E20 = *(const uint4*)&g_E2b[(size_t)(n0 + bn) * 4];      // h0, h1
    uint4 E21 = *(const uint4*)&g_E2b[(size_t)(n0 + bn) * 4 + 2];  // h2, h3

    // ---- mma mapping: warp -> (row-group rg, head hh) ----
    const int rg = wid >> 2, hh = wid & 3;
    const uint32_t pA = sb + OFF_P + hh * P_PLANE
                      + (rg * 16 + (lane & 15)) * P_STRIDE + ((lane >> 4) * 16);
    const uint32_t pB = sb + OFF_S + (lane & 15) * S_STRIDE + hh * 128;

    float acc[8][4];
    #pragma unroll
    for (int i = 0; i < 8; i++)
        #pragma unroll
        for (int j = 0; j < 4; j++) acc[i][j] = 0.f;
    float den[4] = {0.f, 0.f, 0.f, 0.f};
    const uint32_t ones2 = 0x3F803F80u;   // bf16x2 (1.0, 1.0)

    const float* arow = adj + (size_t)(n0 + bn) * N_NODES + bq * 8;

    for (int ch = 0; ch < N_NODES / 64; ch++) {
        const int m0 = ch * 64;
        __syncthreads();   // prior MMA done reading S/P

        // stage S chunk
        #pragma unroll
        for (int i = 0; i < 4; i++) {
            int idx = tid + i * 512;
            int r = idx >> 5, c = idx & 31;
            *(uint4*)(smem + OFF_S + r * S_STRIDE + c * 16) =
                ((const uint4*)g_support_bf)[(size_t)(m0 + r) * 32 + c];
        }

        // build P planes
        {
            float4 av0 = *(const float4*)(arow + m0);
            float4 av1 = *(const float4*)(arow + m0 + 4);
            float aa[8] = {av0.x, av0.y, av0.z, av0.w, av1.x, av1.y, av1.z, av1.w};
            #pragma unroll
            for (int j = 0; j < 4; j++) {
                __nv_bfloat162 adjp = __floats2bfloat162_rn(aa[2 * j], aa[2 * j + 1]);
                const int mpl = bq * 4 + j;
                const size_t mpg = (size_t)((m0 >> 1) + mpl) * 4;
                uint4 A0 = *(const uint4*)&g_E1b[mpg];       // h0: (x,y) h1: (z,w)
                uint4 A1 = *(const uint4*)&g_E1b[mpg + 2];   // h2, h3
                __nv_bfloat162 w0 = __hmul2(__hmax2(__hmul2(b2(A0.x), b2(E20.x)),
                                                    __hmul2(b2(A0.y), b2(E20.y))), adjp);
                __nv_bfloat162 w1 = __hmul2(__hmax2(__hmul2(b2(A0.z), b2(E20.z)),
                                                    __hmul2(b2(A0.w), b2(E20.w))), adjp);
                __nv_bfloat162 w2 = __hmul2(__hmax2(__hmul2(b2(A1.x), b2(E21.x)),
                                                    __hmul2(b2(A1.y), b2(E21.y))), adjp);
                __nv_bfloat162 w3 = __hmul2(__hmax2(__hmul2(b2(A1.z), b2(E21.z)),
                                                    __hmul2(b2(A1.w), b2(E21.w))), adjp);
                const uint32_t po = sb + OFF_P + bn * P_STRIDE + mpl * 4;
                *(uint32_t*)(smem + (po - sb))                 = *(uint32_t*)&w0;
                *(uint32_t*)(smem + (po - sb) + P_PLANE)       = *(uint32_t*)&w1;
                *(uint32_t*)(smem + (po - sb) + 2 * P_PLANE)   = *(uint32_t*)&w2;
                *(uint32_t*)(smem + (po - sb) + 3 * P_PLANE)   = *(uint32_t*)&w3;
            }
        }
        __syncthreads();   // S + P visible

        // MMA phase
        uint32_t a[4], b[2];
        #pragma unroll
        for (int k = 0; k < 4; k++) {
            ldsm_x4(a, pA + k * 32);
            uint32_t baddr = pB + k * 16 * S_STRIDE;
            #pragma unroll
            for (int nf = 0; nf < 8; nf++) {
                ldsm_x2t(b, baddr);
                baddr += 16;
                mma_bf16(acc[nf], a, b[0], b[1]);
            }
            mma_bf16(den, a, ones2, ones2);
        }
    }

    // ---- epilogue: out += num / den ----
    const float i0 = 1.f / den[0];
    const float i1 = 1.f / den[2];
    const int r0 = n0 + rg * 16 + (lane >> 2);
    const int c0 = hh * 64 + (lane & 3) * 2;
    #pragma unroll
    for (int nf = 0; nf < 8; nf++) {
        const int c = c0 + nf * 8;
        float2 o0 = *(float2*)&out[(size_t)r0 * HO + c];
        o0.x += acc[nf][0] * i0; o0.y += acc[nf][1] * i0;
        *(float2*)&out[(size_t)r0 * HO + c] = o0;
        float2 o1 = *(float2*)&out[(size_t)(r0 + 8) * HO + c];
        o1.x += acc[nf][2] * i1; o1.y += acc[nf][3] * i1;
        *(float2*)&out[(size_t)(r0 + 8) * HO + c] = o1;
    }
}

// ---------------------------------------------------------------------------
extern "C" void kernel_launch(void* const* d_in, const int* in_sizes, int n_in,
                              void* d_out, int out_size)
{
    (void)in_sizes; (void)n_in; (void)out_size;
    const float* inputs = (const float*)d_in[0];
    const float* adj    = (const float*)d_in[1];
    const float* weight = (const float*)d_in[2];
    const float* wu     = (const float*)d_in[3];
    const float* wv     = (const float*)d_in[4];
    const float* bias   = (const float*)d_in[5];
    const float* projw  = (const float*)d_in[6];
    const float* projb  = (const float*)d_in[7];
    float* out = (float*)d_out;

    cudaFuncSetAttribute(agg_kernel, cudaFuncAttributeMaxDynamicSharedMemorySize, SMEM_AGG);

    gemm_kernel<<<dim3(512 / 128, N_NODES / 128), 256>>>(inputs, weight, projw, bias, projb, out);
    fvec_kernel<<<(NHEAD * N_NODES) / 8, 256>>>(wu, wv);
    pack_kernel<<<(E1B_N + E2B_N + 255) / 256, 256>>>();
    agg_kernel<<<N_NODES / 64, 512, SMEM_AGG>>>(adj, out);
}